// round 1
// baseline (speedup 1.0000x reference)
#include <cuda_runtime.h>
#include <cuda_bf16.h>

// Problem constants (fixed by the dataset)
#define D     128
#define HID   256
#define KIN   384          // 3*D concatenated input
#define TM    64           // rows (edges / nodes) per block
#define TK    16           // K-chunk of streamed weights
#define NTHR  512          // threads per block (16 warps)
#define ASTRIDE 388        // smem row stride for A tile (bank-friendly, 4-aligned)
#define MAX_NODES 50000

// Scratch: segment-sum aggregates (allowed: __device__ globals, no runtime alloc)
__device__ float g_sent_agg[MAX_NODES * D];
__device__ float g_recv_agg[MAX_NODES * D];

// ---------------------------------------------------------------------------
__global__ void zero_agg_kernel(int total)
{
    int idx = blockIdx.x * blockDim.x + threadIdx.x;
    int stride = gridDim.x * blockDim.x;
    for (int i = idx; i < total; i += stride) {
        g_sent_agg[i] = 0.0f;
        g_recv_agg[i] = 0.0f;
    }
}

// ---------------------------------------------------------------------------
// Shared-memory layout (dynamic):
//   As   : TM * ASTRIDE floats        (input rows, 384 cols)
//   Hs   : TM * HID floats            (hidden after relu)
//   Ws   : TK * HID floats            (streamed weight chunk; stage2 reuses)
//   bs1  : HID floats
//   bs2  : D floats
//   sid  : TM ints
//   rid  : TM ints
#define SMEM_FLOATS (TM*ASTRIDE + TM*HID + TK*HID + HID + D)
#define SMEM_BYTES  (SMEM_FLOATS*4 + 2*TM*4)

// ---------------------------------------------------------------------------
__global__ __launch_bounds__(NTHR, 1)
void edge_mlp_kernel(const float* __restrict__ node_feat,
                     const float* __restrict__ edge_feat,
                     const int*   __restrict__ senders,
                     const int*   __restrict__ receivers,
                     const float* __restrict__ W1,
                     const float* __restrict__ b1,
                     const float* __restrict__ W2,
                     const float* __restrict__ b2,
                     float* __restrict__ new_edges,
                     int E)
{
    extern __shared__ float smem[];
    float* As  = smem;
    float* Hs  = As + TM * ASTRIDE;
    float* Ws  = Hs + TM * HID;
    float* bs1 = Ws + TK * HID;
    float* bs2 = bs1 + HID;
    int*   sid = (int*)(bs2 + D);
    int*   rid = sid + TM;

    const int tid = threadIdx.x;
    const int tx  = tid & 31;     // lane
    const int ty  = tid >> 5;     // warp id, 0..15
    const int e0  = blockIdx.x * TM;

    // --- ids + biases ---
    for (int i = tid; i < TM; i += NTHR) {
        int e = e0 + i;
        sid[i] = (e < E) ? senders[e]   : 0;
        rid[i] = (e < E) ? receivers[e] : 0;
    }
    for (int i = tid; i < HID; i += NTHR) bs1[i] = b1[i];
    for (int i = tid; i < D;   i += NTHR) bs2[i] = b2[i];
    __syncthreads();

    // --- gather input tile: [edge_feat | node_feat[s] | node_feat[r]] ---
    for (int idx = tid; idx < TM * KIN; idx += NTHR) {
        int row = idx / KIN;
        int col = idx - row * KIN;
        int e = e0 + row;
        float v = 0.0f;
        if (e < E) {
            if (col < D)            v = edge_feat[(size_t)e * D + col];
            else if (col < 2 * D)   v = node_feat[(size_t)sid[row] * D + (col - D)];
            else                    v = node_feat[(size_t)rid[row] * D + (col - 2 * D)];
        }
        As[row * ASTRIDE + col] = v;
    }

    // --- stage 1: H = relu(A @ W1 + b1), A[64,384] W1[384,256] ---
    float acc[4][8];
    #pragma unroll
    for (int i = 0; i < 4; ++i)
        #pragma unroll
        for (int j = 0; j < 8; ++j)
            acc[i][j] = bs1[tx + 32 * j];

    for (int kb = 0; kb < KIN; kb += TK) {
        __syncthreads();
        #pragma unroll 2
        for (int idx = tid; idx < TK * HID; idx += NTHR) {
            int kr = idx >> 8;          // /HID
            int c  = idx & (HID - 1);
            Ws[idx] = W1[(size_t)(kb + kr) * HID + c];
        }
        __syncthreads();
        #pragma unroll
        for (int k = 0; k < TK; ++k) {
            float a[4], b[8];
            #pragma unroll
            for (int i = 0; i < 4; ++i) a[i] = As[(ty + 16 * i) * ASTRIDE + kb + k];
            #pragma unroll
            for (int j = 0; j < 8; ++j) b[j] = Ws[k * HID + tx + 32 * j];
            #pragma unroll
            for (int i = 0; i < 4; ++i)
                #pragma unroll
                for (int j = 0; j < 8; ++j)
                    acc[i][j] = fmaf(a[i], b[j], acc[i][j]);
        }
    }
    __syncthreads();
    #pragma unroll
    for (int i = 0; i < 4; ++i)
        #pragma unroll
        for (int j = 0; j < 8; ++j)
            Hs[(ty + 16 * i) * HID + tx + 32 * j] = fmaxf(acc[i][j], 0.0f);
    __syncthreads();

    // --- stage 2: Y = H @ W2 + b2, H[64,256] W2[256,128] ---
    float acc2[4][4];
    #pragma unroll
    for (int i = 0; i < 4; ++i)
        #pragma unroll
        for (int j = 0; j < 4; ++j)
            acc2[i][j] = bs2[tx + 32 * j];

    for (int kb = 0; kb < HID; kb += TK) {
        __syncthreads();
        for (int idx = tid; idx < TK * D; idx += NTHR) {
            int kr = idx >> 7;          // /D
            int c  = idx & (D - 1);
            Ws[idx] = W2[(size_t)(kb + kr) * D + c];
        }
        __syncthreads();
        #pragma unroll
        for (int k = 0; k < TK; ++k) {
            float a[4], b[4];
            #pragma unroll
            for (int i = 0; i < 4; ++i) a[i] = Hs[(ty + 16 * i) * HID + kb + k];
            #pragma unroll
            for (int j = 0; j < 4; ++j) b[j] = Ws[k * D + tx + 32 * j];
            #pragma unroll
            for (int i = 0; i < 4; ++i)
                #pragma unroll
                for (int j = 0; j < 4; ++j)
                    acc2[i][j] = fmaf(a[i], b[j], acc2[i][j]);
        }
    }

    // --- epilogue: write new_edges + fused segment-sum atomics ---
    #pragma unroll
    for (int i = 0; i < 4; ++i) {
        int row = ty + 16 * i;
        int e = e0 + row;
        if (e < E) {
            int s = sid[row], r = rid[row];
            #pragma unroll
            for (int j = 0; j < 4; ++j) {
                int c = tx + 32 * j;
                float v = acc2[i][j];
                new_edges[(size_t)e * D + c] = v;
                atomicAdd(&g_sent_agg[(size_t)s * D + c], v);
                atomicAdd(&g_recv_agg[(size_t)r * D + c], v);
            }
        }
    }
}

// ---------------------------------------------------------------------------
__global__ __launch_bounds__(NTHR, 1)
void node_mlp_kernel(const float* __restrict__ node_feat,
                     const float* __restrict__ W1,
                     const float* __restrict__ b1,
                     const float* __restrict__ W2,
                     const float* __restrict__ b2,
                     float* __restrict__ new_nodes,
                     int N)
{
    extern __shared__ float smem[];
    float* As  = smem;
    float* Hs  = As + TM * ASTRIDE;
    float* Ws  = Hs + TM * HID;
    float* bs1 = Ws + TK * HID;
    float* bs2 = bs1 + HID;

    const int tid = threadIdx.x;
    const int tx  = tid & 31;
    const int ty  = tid >> 5;
    const int n0  = blockIdx.x * TM;

    for (int i = tid; i < HID; i += NTHR) bs1[i] = b1[i];
    for (int i = tid; i < D;   i += NTHR) bs2[i] = b2[i];

    // gather input tile: [node_feat | sent_agg | recv_agg]
    for (int idx = tid; idx < TM * KIN; idx += NTHR) {
        int row = idx / KIN;
        int col = idx - row * KIN;
        int n = n0 + row;
        float v = 0.0f;
        if (n < N) {
            if (col < D)            v = node_feat[(size_t)n * D + col];
            else if (col < 2 * D)   v = g_sent_agg[(size_t)n * D + (col - D)];
            else                    v = g_recv_agg[(size_t)n * D + (col - 2 * D)];
        }
        As[row * ASTRIDE + col] = v;
    }

    float acc[4][8];
    #pragma unroll
    for (int i = 0; i < 4; ++i)
        #pragma unroll
        for (int j = 0; j < 8; ++j)
            acc[i][j] = bs1[tx + 32 * j];

    for (int kb = 0; kb < KIN; kb += TK) {
        __syncthreads();
        #pragma unroll 2
        for (int idx = tid; idx < TK * HID; idx += NTHR) {
            int kr = idx >> 8;
            int c  = idx & (HID - 1);
            Ws[idx] = W1[(size_t)(kb + kr) * HID + c];
        }
        __syncthreads();
        #pragma unroll
        for (int k = 0; k < TK; ++k) {
            float a[4], b[8];
            #pragma unroll
            for (int i = 0; i < 4; ++i) a[i] = As[(ty + 16 * i) * ASTRIDE + kb + k];
            #pragma unroll
            for (int j = 0; j < 8; ++j) b[j] = Ws[k * HID + tx + 32 * j];
            #pragma unroll
            for (int i = 0; i < 4; ++i)
                #pragma unroll
                for (int j = 0; j < 8; ++j)
                    acc[i][j] = fmaf(a[i], b[j], acc[i][j]);
        }
    }
    __syncthreads();
    #pragma unroll
    for (int i = 0; i < 4; ++i)
        #pragma unroll
        for (int j = 0; j < 8; ++j)
            Hs[(ty + 16 * i) * HID + tx + 32 * j] = fmaxf(acc[i][j], 0.0f);
    __syncthreads();

    float acc2[4][4];
    #pragma unroll
    for (int i = 0; i < 4; ++i)
        #pragma unroll
        for (int j = 0; j < 4; ++j)
            acc2[i][j] = bs2[tx + 32 * j];

    for (int kb = 0; kb < HID; kb += TK) {
        __syncthreads();
        for (int idx = tid; idx < TK * D; idx += NTHR) {
            int kr = idx >> 7;
            int c  = idx & (D - 1);
            Ws[idx] = W2[(size_t)(kb + kr) * D + c];
        }
        __syncthreads();
        #pragma unroll
        for (int k = 0; k < TK; ++k) {
            float a[4], b[4];
            #pragma unroll
            for (int i = 0; i < 4; ++i) a[i] = Hs[(ty + 16 * i) * HID + kb + k];
            #pragma unroll
            for (int j = 0; j < 4; ++j) b[j] = Ws[k * D + tx + 32 * j];
            #pragma unroll
            for (int i = 0; i < 4; ++i)
                #pragma unroll
                for (int j = 0; j < 4; ++j)
                    acc2[i][j] = fmaf(a[i], b[j], acc2[i][j]);
        }
    }

    #pragma unroll
    for (int i = 0; i < 4; ++i) {
        int row = ty + 16 * i;
        int n = n0 + row;
        if (n < N) {
            #pragma unroll
            for (int j = 0; j < 4; ++j) {
                int c = tx + 32 * j;
                new_nodes[(size_t)n * D + c] = acc2[i][j];
            }
        }
    }
}

// ---------------------------------------------------------------------------
extern "C" void kernel_launch(void* const* d_in, const int* in_sizes, int n_in,
                              void* d_out, int out_size)
{
    const float* node_feat = (const float*)d_in[0];
    const float* edge_feat = (const float*)d_in[1];
    const int*   senders   = (const int*)  d_in[2];
    const int*   receivers = (const int*)  d_in[3];
    const float* eW1 = (const float*)d_in[4];
    const float* eb1 = (const float*)d_in[5];
    const float* eW2 = (const float*)d_in[6];
    const float* eb2 = (const float*)d_in[7];
    const float* nW1 = (const float*)d_in[8];
    const float* nb1 = (const float*)d_in[9];
    const float* nW2 = (const float*)d_in[10];
    const float* nb2 = (const float*)d_in[11];

    const int N = in_sizes[0] / D;   // 50000
    const int E = in_sizes[2];       // 600000

    float* new_nodes = (float*)d_out;            // output tuple order: (new_nodes, new_edges)
    float* new_edges = new_nodes + (size_t)N * D;

    // Dynamic smem opt-in (idempotent; no allocation involved)
    cudaFuncSetAttribute(edge_mlp_kernel,
                         cudaFuncAttributeMaxDynamicSharedMemorySize, SMEM_BYTES);
    cudaFuncSetAttribute(node_mlp_kernel,
                         cudaFuncAttributeMaxDynamicSharedMemorySize, SMEM_BYTES);

    // 1) zero aggregates
    zero_agg_kernel<<<512, 256>>>(N * D);

    // 2) edge MLP + fused segment-sum
    int eblocks = (E + TM - 1) / TM;
    edge_mlp_kernel<<<eblocks, NTHR, SMEM_BYTES>>>(
        node_feat, edge_feat, senders, receivers,
        eW1, eb1, eW2, eb2, new_edges, E);

    // 3) node MLP
    int nblocks = (N + TM - 1) / TM;
    node_mlp_kernel<<<nblocks, NTHR, SMEM_BYTES>>>(
        node_feat, nW1, nb1, nW2, nb2, new_nodes, N);
}

// round 5
// speedup vs baseline: 3.6495x; 3.6495x over previous
#include <cuda_runtime.h>
#include <cstdint>

#define D     128
#define HID   256
#define KIN   384
#define TM    128
#define NTHR  512
#define MAXN  50000

// -------------------- device scratch --------------------
__device__ float g_sent_agg[MAXN * D];
__device__ float g_recv_agg[MAXN * D];
__device__ float g_ew1t[HID * KIN];   // W1^T [256,384] tf32-rounded
__device__ float g_ew2t[D * HID];     // W2^T [128,256]
__device__ float g_nw1t[HID * KIN];
__device__ float g_nw2t[D * HID];

__device__ __forceinline__ uint32_t f2tf32(float f) {
    uint32_t r;
    asm("cvt.rna.tf32.f32 %0, %1;" : "=r"(r) : "f"(f));
    return r;
}

__device__ __forceinline__ void mma8(float d[4], const uint32_t a[4], const uint32_t b[2]) {
    asm volatile("mma.sync.aligned.m16n8k8.row.col.f32.tf32.tf32.f32 "
                 "{%0,%1,%2,%3}, {%4,%5,%6,%7}, {%8,%9}, {%0,%1,%2,%3};"
                 : "+f"(d[0]), "+f"(d[1]), "+f"(d[2]), "+f"(d[3])
                 : "r"(a[0]), "r"(a[1]), "r"(a[2]), "r"(a[3]),
                   "r"(b[0]), "r"(b[1]));
}

__device__ __forceinline__ void red_add_v4(float* p, float4 v) {
    asm volatile("red.global.add.v4.f32 [%0], {%1,%2,%3,%4};"
                 :: "l"(p), "f"(v.x), "f"(v.y), "f"(v.z), "f"(v.w) : "memory");
}

// -------------------- weight prep --------------------
__global__ void prep_weights(const float* __restrict__ eW1, const float* __restrict__ eW2,
                             const float* __restrict__ nW1, const float* __restrict__ nW2)
{
    int idx0 = blockIdx.x * blockDim.x + threadIdx.x;
    int stride = gridDim.x * blockDim.x;
    for (int i = idx0; i < HID * KIN; i += stride) {
        int n = i / KIN, k = i - n * KIN;
        g_ew1t[i] = __uint_as_float(f2tf32(eW1[k * HID + n]));
        g_nw1t[i] = __uint_as_float(f2tf32(nW1[k * HID + n]));
    }
    for (int i = idx0; i < D * HID; i += stride) {
        int n = i / HID, k = i - n * HID;
        g_ew2t[i] = __uint_as_float(f2tf32(eW2[k * D + n]));
        g_nw2t[i] = __uint_as_float(f2tf32(nW2[k * D + n]));
    }
}

// -------------------- smem layout (float offsets) --------------------
// Stage1: As0/As1 [128][36], Bs0/Bs1 [256][36]
// Stage2: Hs [128][264] aliases As/Bs; Bs2x2 [128][36] after
// Epilogue: Hs2 [128][132] aliases Hs (after stage2 sync)
#define OFF_AS0   0
#define OFF_AS1   4608
#define OFF_BS0   9216
#define OFF_BS1   18432
#define OFF_HS    0
#define HS_STRIDE 264
#define OFF_BS2_0 33792
#define OFF_BS2_1 38400
#define OFF_HS2   0
#define HS2_STRIDE 132
#define OFF_B1S   43008
#define OFF_B2S   43264
#define OFF_SID   43392
#define OFF_RID   43520
#define SMEM_FLOATS 43648
#define SMEM_BYTES (SMEM_FLOATS * 4)

// -------------------- fused MLP kernel --------------------
// mode 0: edge MLP (+ fused segment-sum), mode 1: node MLP
__global__ __launch_bounds__(NTHR, 1)
void gn_mlp_kernel(const float* __restrict__ in0,
                   const float* __restrict__ edge_feat,
                   const int*   __restrict__ senders,
                   const int*   __restrict__ receivers,
                   const float* __restrict__ b1,
                   const float* __restrict__ b2,
                   float* __restrict__ out,
                   int M_total, int mode)
{
    extern __shared__ float sm[];
    float* b1s = sm + OFF_B1S;
    float* b2s = sm + OFF_B2S;
    int*   sid = (int*)(sm + OFF_SID);
    int*   rid = (int*)(sm + OFF_RID);

    const int tid  = threadIdx.x;
    const int lane = tid & 31;
    const int w    = tid >> 5;
    const int g    = lane >> 2;        // group 0..7
    const int t    = lane & 3;         // thread-in-group 0..3
    const int mw   = w & 3;            // M tile (32 rows)
    const int nw   = w >> 2;           // N tile
    const int m0   = blockIdx.x * TM;

    // device-side weight selection (NOT host-passed __device__ symbols)
    const float* __restrict__ w1t = (mode == 0) ? g_ew1t : g_nw1t;
    const float* __restrict__ w2t = (mode == 0) ? g_ew2t : g_nw2t;

    for (int i = tid; i < HID; i += NTHR) b1s[i] = b1[i];
    for (int i = tid; i < D;   i += NTHR) b2s[i] = b2[i];
    if (mode == 0) {
        for (int i = tid; i < TM; i += NTHR) {
            int e = m0 + i;
            sid[i] = (e < M_total) ? senders[e]   : 0;
            rid[i] = (e < M_total) ? receivers[e] : 0;
        }
    }
    __syncthreads();

    // ---- loaders (chunk = 32 cols) ----
    auto load_A = [&](int c, float* dst) {
        #pragma unroll 1
        for (int seg = tid; seg < TM * 8; seg += NTHR) {
            int row = seg >> 3, sc = seg & 7;
            int m = m0 + row;
            float4 v = make_float4(0.f, 0.f, 0.f, 0.f);
            if (m < M_total) {
                const float* src;
                if (mode == 0) {
                    if (c < 4)      src = edge_feat + (size_t)m * D + c * 32;
                    else if (c < 8) src = in0 + (size_t)sid[row] * D + (c - 4) * 32;
                    else            src = in0 + (size_t)rid[row] * D + (c - 8) * 32;
                } else {
                    if (c < 4)      src = in0 + (size_t)m * D + c * 32;
                    else if (c < 8) src = g_sent_agg + (size_t)m * D + (c - 4) * 32;
                    else            src = g_recv_agg + (size_t)m * D + (c - 8) * 32;
                }
                v = *(const float4*)(src + sc * 4);
            }
            uint4 tv;
            tv.x = f2tf32(v.x); tv.y = f2tf32(v.y); tv.z = f2tf32(v.z); tv.w = f2tf32(v.w);
            *(uint4*)(dst + row * 36 + sc * 4) = tv;
        }
    };
    auto load_B1 = [&](int c, float* dst) {
        #pragma unroll 1
        for (int seg = tid; seg < HID * 8; seg += NTHR) {
            int row = seg >> 3, sc = seg & 7;
            float4 v = *(const float4*)(w1t + (size_t)row * KIN + c * 32 + sc * 4);
            *(float4*)(dst + row * 36 + sc * 4) = v;
        }
    };
    auto load_B2 = [&](int c, float* dst) {
        #pragma unroll 1
        for (int seg = tid; seg < D * 8; seg += NTHR) {
            int row = seg >> 3, sc = seg & 7;
            float4 v = *(const float4*)(w2t + (size_t)row * HID + c * 32 + sc * 4);
            *(float4*)(dst + row * 36 + sc * 4) = v;
        }
    };

    // ============ stage 1: [128,384] @ W1^T -> [128,256]; warp tile 32x64 ============
    float acc[2][8][4];
    {
        const int n0 = nw * 64;
        #pragma unroll
        for (int mi = 0; mi < 2; ++mi)
            #pragma unroll
            for (int ni = 0; ni < 8; ++ni) {
                float bv0 = b1s[n0 + ni * 8 + 2 * t];
                float bv1 = b1s[n0 + ni * 8 + 2 * t + 1];
                acc[mi][ni][0] = bv0; acc[mi][ni][1] = bv1;
                acc[mi][ni][2] = bv0; acc[mi][ni][3] = bv1;
            }
    }

    load_A(0, sm + OFF_AS0);
    load_B1(0, sm + OFF_BS0);
    __syncthreads();

    #pragma unroll 1
    for (int c = 0; c < 12; ++c) {
        if (c < 11) {
            load_A(c + 1, sm + ((c + 1) & 1 ? OFF_AS1 : OFF_AS0));
            load_B1(c + 1, sm + ((c + 1) & 1 ? OFF_BS1 : OFF_BS0));
        }
        const float* Ab = sm + ((c & 1) ? OFF_AS1 : OFF_AS0);
        const float* Bb = sm + ((c & 1) ? OFF_BS1 : OFF_BS0);
        #pragma unroll
        for (int kk = 0; kk < 4; ++kk) {
            const int k = kk * 8;
            uint32_t af[2][4], bf[8][2];
            #pragma unroll
            for (int mi = 0; mi < 2; ++mi) {
                int r = mw * 32 + mi * 16;
                af[mi][0] = __float_as_uint(Ab[(r + g) * 36 + k + t]);
                af[mi][1] = __float_as_uint(Ab[(r + 8 + g) * 36 + k + t]);
                af[mi][2] = __float_as_uint(Ab[(r + g) * 36 + k + t + 4]);
                af[mi][3] = __float_as_uint(Ab[(r + 8 + g) * 36 + k + t + 4]);
            }
            #pragma unroll
            for (int ni = 0; ni < 8; ++ni) {
                int n = nw * 64 + ni * 8;
                bf[ni][0] = __float_as_uint(Bb[(n + g) * 36 + k + t]);
                bf[ni][1] = __float_as_uint(Bb[(n + g) * 36 + k + t + 4]);
            }
            #pragma unroll
            for (int mi = 0; mi < 2; ++mi)
                #pragma unroll
                for (int ni = 0; ni < 8; ++ni)
                    mma8(acc[mi][ni], af[mi], bf[ni]);
        }
        __syncthreads();
    }

    // ============ hidden: relu + tf32, store to Hs (aliases As/Bs) ============
    {
        float* Hs = sm + OFF_HS;
        #pragma unroll
        for (int mi = 0; mi < 2; ++mi) {
            int r = mw * 32 + mi * 16;
            #pragma unroll
            for (int ni = 0; ni < 8; ++ni) {
                int n = nw * 64 + ni * 8 + 2 * t;
                Hs[(r + g) * HS_STRIDE + n]     = __uint_as_float(f2tf32(fmaxf(acc[mi][ni][0], 0.f)));
                Hs[(r + g) * HS_STRIDE + n + 1] = __uint_as_float(f2tf32(fmaxf(acc[mi][ni][1], 0.f)));
                Hs[(r + 8 + g) * HS_STRIDE + n]     = __uint_as_float(f2tf32(fmaxf(acc[mi][ni][2], 0.f)));
                Hs[(r + 8 + g) * HS_STRIDE + n + 1] = __uint_as_float(f2tf32(fmaxf(acc[mi][ni][3], 0.f)));
            }
        }
    }
    __syncthreads();

    // ============ stage 2: H[128,256] @ W2^T -> [128,128]; warp tile 32x32 ============
    float acc2[2][4][4];
    {
        const int n0 = nw * 32;
        #pragma unroll
        for (int mi = 0; mi < 2; ++mi)
            #pragma unroll
            for (int ni = 0; ni < 4; ++ni) {
                float bv0 = b2s[n0 + ni * 8 + 2 * t];
                float bv1 = b2s[n0 + ni * 8 + 2 * t + 1];
                acc2[mi][ni][0] = bv0; acc2[mi][ni][1] = bv1;
                acc2[mi][ni][2] = bv0; acc2[mi][ni][3] = bv1;
            }
    }

    load_B2(0, sm + OFF_BS2_0);
    __syncthreads();

    const float* Hs = sm + OFF_HS;
    #pragma unroll 1
    for (int c = 0; c < 8; ++c) {
        if (c < 7)
            load_B2(c + 1, sm + ((c + 1) & 1 ? OFF_BS2_1 : OFF_BS2_0));
        const float* Bb = sm + ((c & 1) ? OFF_BS2_1 : OFF_BS2_0);
        #pragma unroll
        for (int kk = 0; kk < 4; ++kk) {
            const int k = kk * 8;
            const int kg = c * 32 + k;
            uint32_t af[2][4], bf[4][2];
            #pragma unroll
            for (int mi = 0; mi < 2; ++mi) {
                int r = mw * 32 + mi * 16;
                af[mi][0] = __float_as_uint(Hs[(r + g) * HS_STRIDE + kg + t]);
                af[mi][1] = __float_as_uint(Hs[(r + 8 + g) * HS_STRIDE + kg + t]);
                af[mi][2] = __float_as_uint(Hs[(r + g) * HS_STRIDE + kg + t + 4]);
                af[mi][3] = __float_as_uint(Hs[(r + 8 + g) * HS_STRIDE + kg + t + 4]);
            }
            #pragma unroll
            for (int ni = 0; ni < 4; ++ni) {
                int n = nw * 32 + ni * 8;
                bf[ni][0] = __float_as_uint(Bb[(n + g) * 36 + k + t]);
                bf[ni][1] = __float_as_uint(Bb[(n + g) * 36 + k + t + 4]);
            }
            #pragma unroll
            for (int mi = 0; mi < 2; ++mi)
                #pragma unroll
                for (int ni = 0; ni < 4; ++ni)
                    mma8(acc2[mi][ni], af[mi], bf[ni]);
        }
        __syncthreads();
    }

    // ============ frags -> Hs2 (aliases Hs; all stage2 reads done) ============
    {
        float* Hs2 = sm + OFF_HS2;
        #pragma unroll
        for (int mi = 0; mi < 2; ++mi) {
            int r = mw * 32 + mi * 16;
            #pragma unroll
            for (int ni = 0; ni < 4; ++ni) {
                int n = nw * 32 + ni * 8 + 2 * t;
                Hs2[(r + g) * HS2_STRIDE + n]     = acc2[mi][ni][0];
                Hs2[(r + g) * HS2_STRIDE + n + 1] = acc2[mi][ni][1];
                Hs2[(r + 8 + g) * HS2_STRIDE + n]     = acc2[mi][ni][2];
                Hs2[(r + 8 + g) * HS2_STRIDE + n + 1] = acc2[mi][ni][3];
            }
        }
    }
    __syncthreads();

    // ============ epilogue: contiguous v4 stores + fused segment-sum ============
    {
        const float* Hs2 = sm + OFF_HS2;
        int r = tid >> 2;          // 0..127
        int q = tid & 3;           // col quarter
        int m = m0 + r;
        if (m < M_total) {
            float* op = out + (size_t)m * D + q * 32;
            const float* hp = Hs2 + r * HS2_STRIDE + q * 32;
            if (mode == 0) {
                float* ps = g_sent_agg + (size_t)sid[r] * D + q * 32;
                float* pr = g_recv_agg + (size_t)rid[r] * D + q * 32;
                #pragma unroll
                for (int i = 0; i < 8; ++i) {
                    float4 v = *(const float4*)(hp + 4 * i);
                    *(float4*)(op + 4 * i) = v;
                    red_add_v4(ps + 4 * i, v);
                    red_add_v4(pr + 4 * i, v);
                }
            } else {
                #pragma unroll
                for (int i = 0; i < 8; ++i)
                    *(float4*)(op + 4 * i) = *(const float4*)(hp + 4 * i);
            }
        }
    }
}

// -------------------- launch --------------------
extern "C" void kernel_launch(void* const* d_in, const int* in_sizes, int n_in,
                              void* d_out, int out_size)
{
    const float* node_feat = (const float*)d_in[0];
    const float* edge_feat = (const float*)d_in[1];
    const int*   senders   = (const int*)  d_in[2];
    const int*   receivers = (const int*)  d_in[3];
    const float* eW1 = (const float*)d_in[4];
    const float* eb1 = (const float*)d_in[5];
    const float* eW2 = (const float*)d_in[6];
    const float* eb2 = (const float*)d_in[7];
    const float* nW1 = (const float*)d_in[8];
    const float* nb1 = (const float*)d_in[9];
    const float* nW2 = (const float*)d_in[10];
    const float* nb2 = (const float*)d_in[11];

    const int N = in_sizes[0] / D;
    const int E = in_sizes[2];

    float* new_nodes = (float*)d_out;
    float* new_edges = new_nodes + (size_t)N * D;

    cudaFuncSetAttribute(gn_mlp_kernel,
                         cudaFuncAttributeMaxDynamicSharedMemorySize, SMEM_BYTES);

    void *pa, *pb;
    cudaGetSymbolAddress(&pa, g_sent_agg);
    cudaGetSymbolAddress(&pb, g_recv_agg);
    cudaMemsetAsync(pa, 0, sizeof(float) * MAXN * D);
    cudaMemsetAsync(pb, 0, sizeof(float) * MAXN * D);

    prep_weights<<<192, 512>>>(eW1, eW2, nW1, nW2);

    int eblocks = (E + TM - 1) / TM;
    gn_mlp_kernel<<<eblocks, NTHR, SMEM_BYTES>>>(
        node_feat, edge_feat, senders, receivers,
        eb1, eb2, new_edges, E, 0);

    int nblocks = (N + TM - 1) / TM;
    gn_mlp_kernel<<<nblocks, NTHR, SMEM_BYTES>>>(
        node_feat, nullptr, nullptr, nullptr,
        nb1, nb2, new_nodes, N, 1);
}

// round 6
// speedup vs baseline: 5.1943x; 1.4233x over previous
#include <cuda_runtime.h>
#include <cstdint>

#define D     128
#define HID   256
#define KIN   384
#define TM    128
#define NTHR  512
#define MAXN  50000

// -------------------- device scratch --------------------
__device__ float g_sent_agg[MAXN * D];
__device__ float g_recv_agg[MAXN * D];
__device__ __align__(16) float g_ew1t[HID * KIN];   // W1^T [256,384] tf32-rounded
__device__ __align__(16) float g_ew2t[D * HID];     // W2^T [128,256]
__device__ __align__(16) float g_nw1t[HID * KIN];
__device__ __align__(16) float g_nw2t[D * HID];

__device__ __forceinline__ uint32_t f2tf32(float f) {
    uint32_t r;
    asm("cvt.rna.tf32.f32 %0, %1;" : "=r"(r) : "f"(f));
    return r;
}

__device__ __forceinline__ void mma8(float d[4], const uint32_t a[4], const uint32_t b[2]) {
    asm volatile("mma.sync.aligned.m16n8k8.row.col.f32.tf32.tf32.f32 "
                 "{%0,%1,%2,%3}, {%4,%5,%6,%7}, {%8,%9}, {%0,%1,%2,%3};"
                 : "+f"(d[0]), "+f"(d[1]), "+f"(d[2]), "+f"(d[3])
                 : "r"(a[0]), "r"(a[1]), "r"(a[2]), "r"(a[3]),
                   "r"(b[0]), "r"(b[1]));
}

__device__ __forceinline__ void red_add_v4(float* p, float4 v) {
    asm volatile("red.global.add.v4.f32 [%0], {%1,%2,%3,%4};"
                 :: "l"(p), "f"(v.x), "f"(v.y), "f"(v.z), "f"(v.w) : "memory");
}

__device__ __forceinline__ void cp16(float* smem_dst, const float* gsrc) {
    uint32_t s = (uint32_t)__cvta_generic_to_shared(smem_dst);
    asm volatile("cp.async.cg.shared.global [%0], [%1], 16;" :: "r"(s), "l"(gsrc));
}
#define CP_COMMIT() asm volatile("cp.async.commit_group;" ::: "memory")
#define CP_WAIT0()  asm volatile("cp.async.wait_group 0;"  ::: "memory")

// -------------------- weight prep --------------------
__global__ void prep_weights(const float* __restrict__ eW1, const float* __restrict__ eW2,
                             const float* __restrict__ nW1, const float* __restrict__ nW2)
{
    int idx0 = blockIdx.x * blockDim.x + threadIdx.x;
    int stride = gridDim.x * blockDim.x;
    for (int i = idx0; i < HID * KIN; i += stride) {
        int n = i / KIN, k = i - n * KIN;
        g_ew1t[i] = __uint_as_float(f2tf32(eW1[k * HID + n]));
        g_nw1t[i] = __uint_as_float(f2tf32(nW1[k * HID + n]));
    }
    for (int i = idx0; i < D * HID; i += stride) {
        int n = i / HID, k = i - n * HID;
        g_ew2t[i] = __uint_as_float(f2tf32(eW2[k * D + n]));
        g_nw2t[i] = __uint_as_float(f2tf32(nW2[k * D + n]));
    }
}

// -------------------- smem layout (float offsets) --------------------
#define OFF_AS0   0
#define OFF_AS1   4608
#define OFF_BS0   9216
#define OFF_BS1   18432
#define OFF_HS    0
#define HS_STRIDE 264
#define OFF_BS2_0 33792
#define OFF_BS2_1 38400
#define OFF_HS2   0
#define HS2_STRIDE 132
#define OFF_B1S   43008
#define OFF_B2S   43264
#define OFF_SID   43392
#define OFF_RID   43520
#define SMEM_FLOATS 43648
#define SMEM_BYTES (SMEM_FLOATS * 4)

// -------------------- fused MLP kernel --------------------
// mode 0: edge MLP (+ fused segment-sum), mode 1: node MLP
__global__ __launch_bounds__(NTHR, 1)
void gn_mlp_kernel(const float* __restrict__ in0,
                   const float* __restrict__ edge_feat,
                   const int*   __restrict__ senders,
                   const int*   __restrict__ receivers,
                   const float* __restrict__ b1,
                   const float* __restrict__ b2,
                   float* __restrict__ out,
                   int M_total, int mode)
{
    extern __shared__ float sm[];
    float* b1s = sm + OFF_B1S;
    float* b2s = sm + OFF_B2S;
    int*   sid = (int*)(sm + OFF_SID);
    int*   rid = (int*)(sm + OFF_RID);

    const int tid  = threadIdx.x;
    const int lane = tid & 31;
    const int w    = tid >> 5;
    const int g    = lane >> 2;        // group 0..7
    const int t    = lane & 3;         // thread-in-group 0..3
    const int mw   = w & 3;            // M tile (32 rows)
    const int nw   = w >> 2;           // N tile
    const int m0   = blockIdx.x * TM;

    const float* __restrict__ w1t = (mode == 0) ? g_ew1t : g_nw1t;
    const float* __restrict__ w2t = (mode == 0) ? g_ew2t : g_nw2t;

    for (int i = tid; i < HID; i += NTHR) b1s[i] = b1[i];
    for (int i = tid; i < D;   i += NTHR) b2s[i] = b2[i];
    if (mode == 0) {
        for (int i = tid; i < TM; i += NTHR) {
            int e = m0 + i;
            sid[i] = (e < M_total) ? senders[e]   : 0;
            rid[i] = (e < M_total) ? receivers[e] : 0;
        }
    }
    __syncthreads();

    // ---- per-thread A-gather geometry: 2 float4 segments (tid, tid+512) ----
    int a_row[2], a_sc[2];
    const float* a_p0[2]; const float* a_p1[2]; const float* a_p2[2];
    bool a_ok[2];
    #pragma unroll
    for (int i = 0; i < 2; ++i) {
        int seg = tid + NTHR * i;
        a_row[i] = seg >> 3; a_sc[i] = seg & 7;
        int m = m0 + a_row[i];
        a_ok[i] = (m < M_total);
        int mm = a_ok[i] ? m : 0;
        if (mode == 0) {
            a_p0[i] = edge_feat + (size_t)mm * D;
            a_p1[i] = in0 + (size_t)sid[a_row[i]] * D;
            a_p2[i] = in0 + (size_t)rid[a_row[i]] * D;
        } else {
            a_p0[i] = in0 + (size_t)mm * D;
            a_p1[i] = g_sent_agg + (size_t)mm * D;
            a_p2[i] = g_recv_agg + (size_t)mm * D;
        }
    }

    float4 a_pre[2];
    auto ldA = [&](int c) {
        int co = (c & 3) * 32;
        #pragma unroll
        for (int i = 0; i < 2; ++i) {
            const float* base = (c < 4) ? a_p0[i] : (c < 8) ? a_p1[i] : a_p2[i];
            a_pre[i] = a_ok[i] ? *(const float4*)(base + co + a_sc[i] * 4)
                               : make_float4(0.f, 0.f, 0.f, 0.f);
        }
    };
    auto stA = [&](float* dst) {
        #pragma unroll
        for (int i = 0; i < 2; ++i) {
            uint4 tv;
            tv.x = f2tf32(a_pre[i].x); tv.y = f2tf32(a_pre[i].y);
            tv.z = f2tf32(a_pre[i].z); tv.w = f2tf32(a_pre[i].w);
            *(uint4*)(dst + a_row[i] * 36 + a_sc[i] * 4) = tv;
        }
    };
    auto cpB1 = [&](int c, float* dst) {
        #pragma unroll
        for (int seg = tid, it = 0; it < 4; seg += NTHR, ++it) {
            int row = seg >> 3, sc = seg & 7;
            cp16(dst + row * 36 + sc * 4, w1t + (size_t)row * KIN + c * 32 + sc * 4);
        }
    };
    auto cpB2 = [&](int c, float* dst) {
        #pragma unroll
        for (int seg = tid, it = 0; it < 2; seg += NTHR, ++it) {
            int row = seg >> 3, sc = seg & 7;
            cp16(dst + row * 36 + sc * 4, w2t + (size_t)row * HID + c * 32 + sc * 4);
        }
    };

    // ============ stage 1: [128,384] @ W1^T -> [128,256]; warp tile 32x64 ============
    float acc[2][8][4];
    {
        const int n0 = nw * 64;
        #pragma unroll
        for (int mi = 0; mi < 2; ++mi)
            #pragma unroll
            for (int ni = 0; ni < 8; ++ni) {
                float bv0 = b1s[n0 + ni * 8 + 2 * t];
                float bv1 = b1s[n0 + ni * 8 + 2 * t + 1];
                acc[mi][ni][0] = bv0; acc[mi][ni][1] = bv1;
                acc[mi][ni][2] = bv0; acc[mi][ni][3] = bv1;
            }
    }

    // prologue: fill buffer 0
    ldA(0);
    cpB1(0, sm + OFF_BS0);
    CP_COMMIT();
    stA(sm + OFF_AS0);
    CP_WAIT0();
    __syncthreads();

    #pragma unroll 1
    for (int c = 0; c < 12; ++c) {
        if (c < 11) {
            ldA(c + 1);                                   // LDG now, STS after MMA
            cpB1(c + 1, sm + ((c + 1) & 1 ? OFF_BS1 : OFF_BS0));
            CP_COMMIT();
        }
        const float* Ab = sm + ((c & 1) ? OFF_AS1 : OFF_AS0);
        const float* Bb = sm + ((c & 1) ? OFF_BS1 : OFF_BS0);
        #pragma unroll
        for (int kk = 0; kk < 4; ++kk) {
            const int k = kk * 8;
            uint32_t af[2][4], bf[8][2];
            #pragma unroll
            for (int mi = 0; mi < 2; ++mi) {
                int r = mw * 32 + mi * 16;
                af[mi][0] = __float_as_uint(Ab[(r + g) * 36 + k + t]);
                af[mi][1] = __float_as_uint(Ab[(r + 8 + g) * 36 + k + t]);
                af[mi][2] = __float_as_uint(Ab[(r + g) * 36 + k + t + 4]);
                af[mi][3] = __float_as_uint(Ab[(r + 8 + g) * 36 + k + t + 4]);
            }
            #pragma unroll
            for (int ni = 0; ni < 8; ++ni) {
                int n = nw * 64 + ni * 8;
                bf[ni][0] = __float_as_uint(Bb[(n + g) * 36 + k + t]);
                bf[ni][1] = __float_as_uint(Bb[(n + g) * 36 + k + t + 4]);
            }
            #pragma unroll
            for (int mi = 0; mi < 2; ++mi)
                #pragma unroll
                for (int ni = 0; ni < 8; ++ni)
                    mma8(acc[mi][ni], af[mi], bf[ni]);
        }
        if (c < 11) {
            stA(sm + ((c + 1) & 1 ? OFF_AS1 : OFF_AS0));
            CP_WAIT0();
        }
        __syncthreads();
    }

    // ============ hidden: relu + tf32, store to Hs (aliases As/Bs) ============
    {
        float* Hs = sm + OFF_HS;
        #pragma unroll
        for (int mi = 0; mi < 2; ++mi) {
            int r = mw * 32 + mi * 16;
            #pragma unroll
            for (int ni = 0; ni < 8; ++ni) {
                int n = nw * 64 + ni * 8 + 2 * t;
                Hs[(r + g) * HS_STRIDE + n]     = __uint_as_float(f2tf32(fmaxf(acc[mi][ni][0], 0.f)));
                Hs[(r + g) * HS_STRIDE + n + 1] = __uint_as_float(f2tf32(fmaxf(acc[mi][ni][1], 0.f)));
                Hs[(r + 8 + g) * HS_STRIDE + n]     = __uint_as_float(f2tf32(fmaxf(acc[mi][ni][2], 0.f)));
                Hs[(r + 8 + g) * HS_STRIDE + n + 1] = __uint_as_float(f2tf32(fmaxf(acc[mi][ni][3], 0.f)));
            }
        }
    }
    __syncthreads();

    // ============ stage 2: H[128,256] @ W2^T -> [128,128]; warp tile 32x32 ============
    float acc2[2][4][4];
    {
        const int n0 = nw * 32;
        #pragma unroll
        for (int mi = 0; mi < 2; ++mi)
            #pragma unroll
            for (int ni = 0; ni < 4; ++ni) {
                float bv0 = b2s[n0 + ni * 8 + 2 * t];
                float bv1 = b2s[n0 + ni * 8 + 2 * t + 1];
                acc2[mi][ni][0] = bv0; acc2[mi][ni][1] = bv1;
                acc2[mi][ni][2] = bv0; acc2[mi][ni][3] = bv1;
            }
    }

    cpB2(0, sm + OFF_BS2_0);
    CP_COMMIT();
    CP_WAIT0();
    __syncthreads();

    const float* Hs = sm + OFF_HS;
    #pragma unroll 1
    for (int c = 0; c < 8; ++c) {
        if (c < 7) {
            cpB2(c + 1, sm + ((c + 1) & 1 ? OFF_BS2_1 : OFF_BS2_0));
            CP_COMMIT();
        }
        const float* Bb = sm + ((c & 1) ? OFF_BS2_1 : OFF_BS2_0);
        #pragma unroll
        for (int kk = 0; kk < 4; ++kk) {
            const int k = kk * 8;
            const int kg = c * 32 + k;
            uint32_t af[2][4], bf[4][2];
            #pragma unroll
            for (int mi = 0; mi < 2; ++mi) {
                int r = mw * 32 + mi * 16;
                af[mi][0] = __float_as_uint(Hs[(r + g) * HS_STRIDE + kg + t]);
                af[mi][1] = __float_as_uint(Hs[(r + 8 + g) * HS_STRIDE + kg + t]);
                af[mi][2] = __float_as_uint(Hs[(r + g) * HS_STRIDE + kg + t + 4]);
                af[mi][3] = __float_as_uint(Hs[(r + 8 + g) * HS_STRIDE + kg + t + 4]);
            }
            #pragma unroll
            for (int ni = 0; ni < 4; ++ni) {
                int n = nw * 32 + ni * 8;
                bf[ni][0] = __float_as_uint(Bb[(n + g) * 36 + k + t]);
                bf[ni][1] = __float_as_uint(Bb[(n + g) * 36 + k + t + 4]);
            }
            #pragma unroll
            for (int mi = 0; mi < 2; ++mi)
                #pragma unroll
                for (int ni = 0; ni < 4; ++ni)
                    mma8(acc2[mi][ni], af[mi], bf[ni]);
        }
        if (c < 7) CP_WAIT0();
        __syncthreads();
    }

    // ============ frags -> Hs2 (aliases Hs; all stage2 reads done) ============
    {
        float* Hs2 = sm + OFF_HS2;
        #pragma unroll
        for (int mi = 0; mi < 2; ++mi) {
            int r = mw * 32 + mi * 16;
            #pragma unroll
            for (int ni = 0; ni < 4; ++ni) {
                int n = nw * 32 + ni * 8 + 2 * t;
                Hs2[(r + g) * HS2_STRIDE + n]     = acc2[mi][ni][0];
                Hs2[(r + g) * HS2_STRIDE + n + 1] = acc2[mi][ni][1];
                Hs2[(r + 8 + g) * HS2_STRIDE + n]     = acc2[mi][ni][2];
                Hs2[(r + 8 + g) * HS2_STRIDE + n + 1] = acc2[mi][ni][3];
            }
        }
    }
    __syncthreads();

    // ============ epilogue: contiguous v4 stores + fused segment-sum ============
    {
        const float* Hs2 = sm + OFF_HS2;
        int r = tid >> 2;
        int q = tid & 3;
        int m = m0 + r;
        if (m < M_total) {
            float* op = out + (size_t)m * D + q * 32;
            const float* hp = Hs2 + r * HS2_STRIDE + q * 32;
            if (mode == 0) {
                float* ps = g_sent_agg + (size_t)sid[r] * D + q * 32;
                float* pr = g_recv_agg + (size_t)rid[r] * D + q * 32;
                #pragma unroll
                for (int i = 0; i < 8; ++i) {
                    float4 v = *(const float4*)(hp + 4 * i);
                    *(float4*)(op + 4 * i) = v;
                    red_add_v4(ps + 4 * i, v);
                    red_add_v4(pr + 4 * i, v);
                }
            } else {
                #pragma unroll
                for (int i = 0; i < 8; ++i)
                    *(float4*)(op + 4 * i) = *(const float4*)(hp + 4 * i);
            }
        }
    }
}

// -------------------- launch --------------------
extern "C" void kernel_launch(void* const* d_in, const int* in_sizes, int n_in,
                              void* d_out, int out_size)
{
    const float* node_feat = (const float*)d_in[0];
    const float* edge_feat = (const float*)d_in[1];
    const int*   senders   = (const int*)  d_in[2];
    const int*   receivers = (const int*)  d_in[3];
    const float* eW1 = (const float*)d_in[4];
    const float* eb1 = (const float*)d_in[5];
    const float* eW2 = (const float*)d_in[6];
    const float* eb2 = (const float*)d_in[7];
    const float* nW1 = (const float*)d_in[8];
    const float* nb1 = (const float*)d_in[9];
    const float* nW2 = (const float*)d_in[10];
    const float* nb2 = (const float*)d_in[11];

    const int N = in_sizes[0] / D;
    const int E = in_sizes[2];

    float* new_nodes = (float*)d_out;
    float* new_edges = new_nodes + (size_t)N * D;

    cudaFuncSetAttribute(gn_mlp_kernel,
                         cudaFuncAttributeMaxDynamicSharedMemorySize, SMEM_BYTES);

    void *pa, *pb;
    cudaGetSymbolAddress(&pa, g_sent_agg);
    cudaGetSymbolAddress(&pb, g_recv_agg);
    cudaMemsetAsync(pa, 0, sizeof(float) * MAXN * D);
    cudaMemsetAsync(pb, 0, sizeof(float) * MAXN * D);

    prep_weights<<<192, 512>>>(eW1, eW2, nW1, nW2);

    int eblocks = (E + TM - 1) / TM;
    gn_mlp_kernel<<<eblocks, NTHR, SMEM_BYTES>>>(
        node_feat, edge_feat, senders, receivers,
        eb1, eb2, new_edges, E, 0);

    int nblocks = (N + TM - 1) / TM;
    gn_mlp_kernel<<<nblocks, NTHR, SMEM_BYTES>>>(
        node_feat, nullptr, nullptr, nullptr,
        nb1, nb2, new_nodes, N, 1);
}

// round 7
// speedup vs baseline: 7.5950x; 1.4622x over previous
#include <cuda_runtime.h>
#include <cuda_fp16.h>
#include <cstdint>

#define D     128
#define HID   256
#define KIN   384
#define TM    128
#define NTHR  512
#define MAXN  50000

// -------------------- device scratch --------------------
__device__ float g_sent_agg[MAXN * D];
__device__ float g_recv_agg[MAXN * D];
__device__ __align__(16) __half g_ew1t[HID * KIN];   // W1^T [256,384] fp16
__device__ __align__(16) __half g_ew2t[D * HID];     // W2^T [128,256]
__device__ __align__(16) __half g_nw1t[HID * KIN];
__device__ __align__(16) __half g_nw2t[D * HID];

__device__ __forceinline__ void mma16(float d[4], const uint32_t a[4], const uint32_t b[2]) {
    asm volatile("mma.sync.aligned.m16n8k16.row.col.f32.f16.f16.f32 "
                 "{%0,%1,%2,%3}, {%4,%5,%6,%7}, {%8,%9}, {%0,%1,%2,%3};"
                 : "+f"(d[0]), "+f"(d[1]), "+f"(d[2]), "+f"(d[3])
                 : "r"(a[0]), "r"(a[1]), "r"(a[2]), "r"(a[3]),
                   "r"(b[0]), "r"(b[1]));
}

__device__ __forceinline__ void red_add_v4(float* p, float4 v) {
    asm volatile("red.global.add.v4.f32 [%0], {%1,%2,%3,%4};"
                 :: "l"(p), "f"(v.x), "f"(v.y), "f"(v.z), "f"(v.w) : "memory");
}

__device__ __forceinline__ void cp16(__half* smem_dst, const __half* gsrc) {
    uint32_t s = (uint32_t)__cvta_generic_to_shared(smem_dst);
    asm volatile("cp.async.cg.shared.global [%0], [%1], 16;" :: "r"(s), "l"(gsrc));
}
#define CP_COMMIT() asm volatile("cp.async.commit_group;" ::: "memory")
#define CP_WAIT0()  asm volatile("cp.async.wait_group 0;"  ::: "memory")

// -------------------- weight prep: transpose + fp16 --------------------
__global__ void prep_weights(const float* __restrict__ eW1, const float* __restrict__ eW2,
                             const float* __restrict__ nW1, const float* __restrict__ nW2)
{
    int idx0 = blockIdx.x * blockDim.x + threadIdx.x;
    int stride = gridDim.x * blockDim.x;
    for (int i = idx0; i < HID * KIN; i += stride) {
        int n = i / KIN, k = i - n * KIN;
        g_ew1t[i] = __float2half_rn(eW1[k * HID + n]);
        g_nw1t[i] = __float2half_rn(nW1[k * HID + n]);
    }
    for (int i = idx0; i < D * HID; i += stride) {
        int n = i / HID, k = i - n * HID;
        g_ew2t[i] = __float2half_rn(eW2[k * D + n]);
        g_nw2t[i] = __float2half_rn(nW2[k * D + n]);
    }
}

// -------------------- smem layout --------------------
// half offsets: As0/As1 [128][40], Bs0/Bs1 [256][40], Hs [128][264] (aliases),
// Bs2 x2 [128][40] after Hs.  float region: Hs2 [128][132] aliases Hs.
#define HAS0   0
#define HAS1   5120
#define HBS0   10240
#define HBS1   20480
#define HHS    0
#define HS_STRIDE_H 264
#define HBS2_0 33792
#define HBS2_1 38912
// float offsets
#define OFF_HS2   0
#define HS2_STRIDE 132
#define OFF_B1S   22016
#define OFF_B2S   22272
#define OFF_SID   22400
#define OFF_RID   22528
#define SMEM_BYTES 90624

// -------------------- fused MLP kernel --------------------
// mode 0: edge MLP (+ fused segment-sum), mode 1: node MLP
__global__ __launch_bounds__(NTHR, 1)
void gn_mlp_kernel(const float* __restrict__ in0,
                   const float* __restrict__ edge_feat,
                   const int*   __restrict__ senders,
                   const int*   __restrict__ receivers,
                   const float* __restrict__ b1,
                   const float* __restrict__ b2,
                   float* __restrict__ out,
                   int M_total, int mode)
{
    extern __shared__ float sm[];
    __half* hsm = (__half*)sm;
    float* b1s = sm + OFF_B1S;
    float* b2s = sm + OFF_B2S;
    int*   sid = (int*)(sm + OFF_SID);
    int*   rid = (int*)(sm + OFF_RID);

    const int tid  = threadIdx.x;
    const int lane = tid & 31;
    const int w    = tid >> 5;
    const int g    = lane >> 2;        // group 0..7
    const int t    = lane & 3;         // thread-in-group 0..3
    const int mw   = w & 3;            // M tile (32 rows)
    const int nw   = w >> 2;           // N tile
    const int m0   = blockIdx.x * TM;

    const __half* __restrict__ w1t = (mode == 0) ? g_ew1t : g_nw1t;
    const __half* __restrict__ w2t = (mode == 0) ? g_ew2t : g_nw2t;

    for (int i = tid; i < HID; i += NTHR) b1s[i] = b1[i];
    for (int i = tid; i < D;   i += NTHR) b2s[i] = b2[i];
    if (mode == 0) {
        for (int i = tid; i < TM; i += NTHR) {
            int e = m0 + i;
            sid[i] = (e < M_total) ? senders[e]   : 0;
            rid[i] = (e < M_total) ? receivers[e] : 0;
        }
    }
    __syncthreads();

    // ---- per-thread A-gather geometry: 2 float4 segments (tid, tid+512) ----
    int a_row[2], a_sc[2];
    const float* a_p0[2]; const float* a_p1[2]; const float* a_p2[2];
    bool a_ok[2];
    #pragma unroll
    for (int i = 0; i < 2; ++i) {
        int seg = tid + NTHR * i;
        a_row[i] = seg >> 3; a_sc[i] = seg & 7;
        int m = m0 + a_row[i];
        a_ok[i] = (m < M_total);
        int mm = a_ok[i] ? m : 0;
        if (mode == 0) {
            a_p0[i] = edge_feat + (size_t)mm * D;
            a_p1[i] = in0 + (size_t)sid[a_row[i]] * D;
            a_p2[i] = in0 + (size_t)rid[a_row[i]] * D;
        } else {
            a_p0[i] = in0 + (size_t)mm * D;
            a_p1[i] = g_sent_agg + (size_t)mm * D;
            a_p2[i] = g_recv_agg + (size_t)mm * D;
        }
    }

    float4 a_pre[2];
    auto ldA = [&](int c) {
        int co = (c & 3) * 32;
        #pragma unroll
        for (int i = 0; i < 2; ++i) {
            const float* base = (c < 4) ? a_p0[i] : (c < 8) ? a_p1[i] : a_p2[i];
            a_pre[i] = a_ok[i] ? *(const float4*)(base + co + a_sc[i] * 4)
                               : make_float4(0.f, 0.f, 0.f, 0.f);
        }
    };
    auto stA = [&](__half* dst) {
        #pragma unroll
        for (int i = 0; i < 2; ++i) {
            __half2 lo = __floats2half2_rn(a_pre[i].x, a_pre[i].y);
            __half2 hi = __floats2half2_rn(a_pre[i].z, a_pre[i].w);
            uint2 tv;
            tv.x = *(uint32_t*)&lo; tv.y = *(uint32_t*)&hi;
            *(uint2*)(dst + a_row[i] * 40 + a_sc[i] * 4) = tv;
        }
    };
    auto cpB1 = [&](int c, __half* dst) {           // 256 rows x 4 segs of 8 halves
        #pragma unroll
        for (int seg = tid, it = 0; it < 2; seg += NTHR, ++it) {
            int row = seg >> 2, sc = seg & 3;
            cp16(dst + row * 40 + sc * 8, w1t + (size_t)row * KIN + c * 32 + sc * 8);
        }
    };
    auto cpB2 = [&](int c, __half* dst) {           // 128 rows x 4 segs
        int row = tid >> 2, sc = tid & 3;
        cp16(dst + row * 40 + sc * 8, w2t + (size_t)row * HID + c * 32 + sc * 8);
    };

    // ============ stage 1: [128,384] @ W1^T -> [128,256]; warp tile 32x64 ============
    float acc[2][8][4];
    {
        const int n0 = nw * 64;
        #pragma unroll
        for (int mi = 0; mi < 2; ++mi)
            #pragma unroll
            for (int ni = 0; ni < 8; ++ni) {
                float bv0 = b1s[n0 + ni * 8 + 2 * t];
                float bv1 = b1s[n0 + ni * 8 + 2 * t + 1];
                acc[mi][ni][0] = bv0; acc[mi][ni][1] = bv1;
                acc[mi][ni][2] = bv0; acc[mi][ni][3] = bv1;
            }
    }

    ldA(0);
    cpB1(0, hsm + HBS0);
    CP_COMMIT();
    stA(hsm + HAS0);
    CP_WAIT0();
    __syncthreads();

    #pragma unroll 1
    for (int c = 0; c < 12; ++c) {
        if (c < 11) {
            ldA(c + 1);
            cpB1(c + 1, hsm + ((c + 1) & 1 ? HBS1 : HBS0));
            CP_COMMIT();
        }
        const __half* Ab = hsm + ((c & 1) ? HAS1 : HAS0);
        const __half* Bb = hsm + ((c & 1) ? HBS1 : HBS0);
        #pragma unroll
        for (int kk = 0; kk < 2; ++kk) {
            const int kh = kk * 16 + 2 * t;
            uint32_t af[2][4], bf[8][2];
            #pragma unroll
            for (int mi = 0; mi < 2; ++mi) {
                int r = mw * 32 + mi * 16;
                af[mi][0] = *(const uint32_t*)(Ab + (r + g) * 40 + kh);
                af[mi][1] = *(const uint32_t*)(Ab + (r + 8 + g) * 40 + kh);
                af[mi][2] = *(const uint32_t*)(Ab + (r + g) * 40 + kh + 8);
                af[mi][3] = *(const uint32_t*)(Ab + (r + 8 + g) * 40 + kh + 8);
            }
            #pragma unroll
            for (int ni = 0; ni < 8; ++ni) {
                int n = nw * 64 + ni * 8;
                bf[ni][0] = *(const uint32_t*)(Bb + (n + g) * 40 + kh);
                bf[ni][1] = *(const uint32_t*)(Bb + (n + g) * 40 + kh + 8);
            }
            #pragma unroll
            for (int mi = 0; mi < 2; ++mi)
                #pragma unroll
                for (int ni = 0; ni < 8; ++ni)
                    mma16(acc[mi][ni], af[mi], bf[ni]);
        }
        if (c < 11) {
            stA(hsm + ((c + 1) & 1 ? HAS1 : HAS0));
            CP_WAIT0();
        }
        __syncthreads();
    }

    // ============ hidden: relu -> fp16, store to Hs (aliases As/Bs) ============
    {
        __half* Hs = hsm + HHS;
        #pragma unroll
        for (int mi = 0; mi < 2; ++mi) {
            int r = mw * 32 + mi * 16;
            #pragma unroll
            for (int ni = 0; ni < 8; ++ni) {
                int n = nw * 64 + ni * 8 + 2 * t;
                __half2 v0 = __floats2half2_rn(fmaxf(acc[mi][ni][0], 0.f), fmaxf(acc[mi][ni][1], 0.f));
                __half2 v1 = __floats2half2_rn(fmaxf(acc[mi][ni][2], 0.f), fmaxf(acc[mi][ni][3], 0.f));
                *(uint32_t*)(Hs + (r + g) * HS_STRIDE_H + n)     = *(uint32_t*)&v0;
                *(uint32_t*)(Hs + (r + 8 + g) * HS_STRIDE_H + n) = *(uint32_t*)&v1;
            }
        }
    }
    __syncthreads();

    // ============ stage 2: H[128,256] @ W2^T -> [128,128]; warp tile 32x32 ============
    float acc2[2][4][4];
    {
        const int n0 = nw * 32;
        #pragma unroll
        for (int mi = 0; mi < 2; ++mi)
            #pragma unroll
            for (int ni = 0; ni < 4; ++ni) {
                float bv0 = b2s[n0 + ni * 8 + 2 * t];
                float bv1 = b2s[n0 + ni * 8 + 2 * t + 1];
                acc2[mi][ni][0] = bv0; acc2[mi][ni][1] = bv1;
                acc2[mi][ni][2] = bv0; acc2[mi][ni][3] = bv1;
            }
    }

    cpB2(0, hsm + HBS2_0);
    CP_COMMIT();
    CP_WAIT0();
    __syncthreads();

    const __half* Hs = hsm + HHS;
    #pragma unroll 1
    for (int c = 0; c < 8; ++c) {
        if (c < 7) {
            cpB2(c + 1, hsm + ((c + 1) & 1 ? HBS2_1 : HBS2_0));
            CP_COMMIT();
        }
        const __half* Bb = hsm + ((c & 1) ? HBS2_1 : HBS2_0);
        #pragma unroll
        for (int kk = 0; kk < 2; ++kk) {
            const int kh = kk * 16 + 2 * t;
            const int kg = c * 32 + kh;
            uint32_t af[2][4], bf[4][2];
            #pragma unroll
            for (int mi = 0; mi < 2; ++mi) {
                int r = mw * 32 + mi * 16;
                af[mi][0] = *(const uint32_t*)(Hs + (r + g) * HS_STRIDE_H + kg);
                af[mi][1] = *(const uint32_t*)(Hs + (r + 8 + g) * HS_STRIDE_H + kg);
                af[mi][2] = *(const uint32_t*)(Hs + (r + g) * HS_STRIDE_H + kg + 8);
                af[mi][3] = *(const uint32_t*)(Hs + (r + 8 + g) * HS_STRIDE_H + kg + 8);
            }
            #pragma unroll
            for (int ni = 0; ni < 4; ++ni) {
                int n = nw * 32 + ni * 8;
                bf[ni][0] = *(const uint32_t*)(Bb + (n + g) * 40 + kh);
                bf[ni][1] = *(const uint32_t*)(Bb + (n + g) * 40 + kh + 8);
            }
            #pragma unroll
            for (int mi = 0; mi < 2; ++mi)
                #pragma unroll
                for (int ni = 0; ni < 4; ++ni)
                    mma16(acc2[mi][ni], af[mi], bf[ni]);
        }
        if (c < 7) CP_WAIT0();
        __syncthreads();
    }

    // ============ frags -> Hs2 fp32 (aliases Hs; stage2 reads done) ============
    {
        float* Hs2 = sm + OFF_HS2;
        #pragma unroll
        for (int mi = 0; mi < 2; ++mi) {
            int r = mw * 32 + mi * 16;
            #pragma unroll
            for (int ni = 0; ni < 4; ++ni) {
                int n = nw * 32 + ni * 8 + 2 * t;
                Hs2[(r + g) * HS2_STRIDE + n]     = acc2[mi][ni][0];
                Hs2[(r + g) * HS2_STRIDE + n + 1] = acc2[mi][ni][1];
                Hs2[(r + 8 + g) * HS2_STRIDE + n]     = acc2[mi][ni][2];
                Hs2[(r + 8 + g) * HS2_STRIDE + n + 1] = acc2[mi][ni][3];
            }
        }
    }
    __syncthreads();

    // ============ epilogue: contiguous v4 stores + fused segment-sum ============
    {
        const float* Hs2 = sm + OFF_HS2;
        int r = tid >> 2;
        int q = tid & 3;
        int m = m0 + r;
        if (m < M_total) {
            float* op = out + (size_t)m * D + q * 32;
            const float* hp = Hs2 + r * HS2_STRIDE + q * 32;
            if (mode == 0) {
                float* ps = g_sent_agg + (size_t)sid[r] * D + q * 32;
                float* pr = g_recv_agg + (size_t)rid[r] * D + q * 32;
                #pragma unroll
                for (int i = 0; i < 8; ++i) {
                    float4 v = *(const float4*)(hp + 4 * i);
                    *(float4*)(op + 4 * i) = v;
                    red_add_v4(ps + 4 * i, v);
                    red_add_v4(pr + 4 * i, v);
                }
            } else {
                #pragma unroll
                for (int i = 0; i < 8; ++i)
                    *(float4*)(op + 4 * i) = *(const float4*)(hp + 4 * i);
            }
        }
    }
}

// -------------------- launch --------------------
extern "C" void kernel_launch(void* const* d_in, const int* in_sizes, int n_in,
                              void* d_out, int out_size)
{
    const float* node_feat = (const float*)d_in[0];
    const float* edge_feat = (const float*)d_in[1];
    const int*   senders   = (const int*)  d_in[2];
    const int*   receivers = (const int*)  d_in[3];
    const float* eW1 = (const float*)d_in[4];
    const float* eb1 = (const float*)d_in[5];
    const float* eW2 = (const float*)d_in[6];
    const float* eb2 = (const float*)d_in[7];
    const float* nW1 = (const float*)d_in[8];
    const float* nb1 = (const float*)d_in[9];
    const float* nW2 = (const float*)d_in[10];
    const float* nb2 = (const float*)d_in[11];

    const int N = in_sizes[0] / D;
    const int E = in_sizes[2];

    float* new_nodes = (float*)d_out;
    float* new_edges = new_nodes + (size_t)N * D;

    cudaFuncSetAttribute(gn_mlp_kernel,
                         cudaFuncAttributeMaxDynamicSharedMemorySize, SMEM_BYTES);

    void *pa, *pb;
    cudaGetSymbolAddress(&pa, g_sent_agg);
    cudaGetSymbolAddress(&pb, g_recv_agg);
    cudaMemsetAsync(pa, 0, sizeof(float) * MAXN * D);
    cudaMemsetAsync(pb, 0, sizeof(float) * MAXN * D);

    prep_weights<<<192, 512>>>(eW1, eW2, nW1, nW2);

    int eblocks = (E + TM - 1) / TM;
    gn_mlp_kernel<<<eblocks, NTHR, SMEM_BYTES>>>(
        node_feat, edge_feat, senders, receivers,
        eb1, eb2, new_edges, E, 0);

    int nblocks = (N + TM - 1) / TM;
    gn_mlp_kernel<<<nblocks, NTHR, SMEM_BYTES>>>(
        node_feat, nullptr, nullptr, nullptr,
        nb1, nb2, new_nodes, N, 1);
}